// round 7
// baseline (speedup 1.0000x reference)
#include <cuda_runtime.h>
#include <math.h>
#include <stdint.h>

// Problem constants (fixed-shape problem)
#define NN 100000
#define EEDGES 1600000
#define NEG_SLOPE 0.2f
#define NBLK_SCAN ((NN + 1023) / 1024)   // 98

// Padded smem strides (floats) for conflict-free mma fragment loads
#define AS_STRIDE 132   // mod 32 = 4
#define WS_STRIDE 136   // mod 32 = 8

// ---------------------------------------------------------------------------
// Scratch (device globals — allocation-free rule)
// ---------------------------------------------------------------------------
__device__ __align__(16) float g_feat[(size_t)NN * 128];   // projected features [N,H,D]
__device__ __align__(16) float g_el[(size_t)NN * 4];       // [N,H]
__device__ __align__(16) float g_er[(size_t)NN * 4];       // [N,H]
__device__ __align__(16) int   g_srcs[EEDGES];             // src id, dst-sorted
__device__ __align__(16) int   g_cnt[NN];                  // per-dst degree
__device__ __align__(16) int   g_off[NN];                  // block-local offsets (cursor after scatter)
__device__ __align__(16) int   g_bsum[NBLK_SCAN + 32];     // per-scan-block totals
__device__ __align__(16) int   g_boff[NBLK_SCAN + 32];     // exclusive scan of block totals

// ---------------------------------------------------------------------------
// tf32 helpers
// ---------------------------------------------------------------------------
__device__ __forceinline__ uint32_t f2tf32(float x) {
    uint32_t r;
    asm("cvt.rna.tf32.f32 %0, %1;" : "=r"(r) : "f"(x));
    return r;
}
__device__ __forceinline__ void split_tf32(float x, uint32_t& hi, uint32_t& lo) {
    hi = f2tf32(x);
    lo = f2tf32(x - __uint_as_float(hi));
}
__device__ __forceinline__ void mma_tf32(float c[4],
                                         uint32_t a0, uint32_t a1, uint32_t a2, uint32_t a3,
                                         uint32_t b0, uint32_t b1) {
    asm("mma.sync.aligned.m16n8k8.row.col.f32.tf32.tf32.f32 "
        "{%0,%1,%2,%3},{%4,%5,%6,%7},{%8,%9},{%0,%1,%2,%3};"
        : "+f"(c[0]), "+f"(c[1]), "+f"(c[2]), "+f"(c[3])
        : "r"(a0), "r"(a1), "r"(a2), "r"(a3), "r"(b0), "r"(b1));
}

// ---------------------------------------------------------------------------
// Kernel: zero degree counters
// ---------------------------------------------------------------------------
__global__ void zero_kernel(int n) {
    int i = blockIdx.x * blockDim.x + threadIdx.x;
    if (i < n) g_cnt[i] = 0;
}

// ---------------------------------------------------------------------------
// Kernel: histogram of dst (4 edges per thread, int4 load)
// ---------------------------------------------------------------------------
__global__ void hist_kernel(const int* __restrict__ dst, int E) {
    int e = (blockIdx.x * blockDim.x + threadIdx.x) * 4;
    if (e + 3 < E) {
        int4 d4 = *(const int4*)(dst + e);
        atomicAdd(&g_cnt[d4.x], 1);
        atomicAdd(&g_cnt[d4.y], 1);
        atomicAdd(&g_cnt[d4.z], 1);
        atomicAdd(&g_cnt[d4.w], 1);
    } else {
        for (int k = e; k < E; k++) atomicAdd(&g_cnt[dst[k]], 1);
    }
}

// ---------------------------------------------------------------------------
// Kernel: GEMM via tensor cores (3xTF32), fused el/er epilogue.
// ---------------------------------------------------------------------------
__global__ void __launch_bounds__(256, 1)
gemm_kernel(const float* __restrict__ A,
            const float* __restrict__ W,
            const float* __restrict__ attn_l,
            const float* __restrict__ attn_r,
            int N) {
    extern __shared__ float sm[];
    float* As = sm;                       // [128][AS_STRIDE]
    float* Ws = sm + 128 * AS_STRIDE;     // [128][WS_STRIDE]  (Ws[k][n])

    int tid = threadIdx.x;
    int rowBase = blockIdx.x * 128;

    for (int i = tid; i < 128 * 32; i += 256) {
        int k = i >> 5, c4 = i & 31;
        float4 v = ((const float4*)W)[(size_t)k * 32 + c4];
        *(float4*)(Ws + k * WS_STRIDE + c4 * 4) = v;
    }
    for (int i = tid; i < 128 * 32; i += 256) {
        int r = i >> 5, c4 = i & 31;
        int gr = rowBase + r;
        float4 v = make_float4(0.f, 0.f, 0.f, 0.f);
        if (gr < N) v = ((const float4*)A)[(size_t)gr * 32 + c4];
        *(float4*)(As + r * AS_STRIDE + c4 * 4) = v;
    }
    __syncthreads();

    int wid  = tid >> 5;
    int lane = tid & 31;
    int grp  = lane >> 2;
    int tig  = lane & 3;
    int warpM = wid >> 1;
    int warpN = wid & 1;

    float C[2][8][4];
#pragma unroll
    for (int mt = 0; mt < 2; mt++)
#pragma unroll
        for (int nt = 0; nt < 8; nt++)
#pragma unroll
            for (int q = 0; q < 4; q++) C[mt][nt][q] = 0.f;

#pragma unroll 2
    for (int step = 0; step < 16; step++) {
        int k0 = step * 8;

        uint32_t Ah[2][4], Al[2][4];
#pragma unroll
        for (int mt = 0; mt < 2; mt++) {
            int mbase = warpM * 32 + mt * 16;
            const float* ap = As + (mbase + grp) * AS_STRIDE + k0 + tig;
            float a0 = ap[0];
            float a1 = ap[8 * AS_STRIDE];
            float a2 = ap[4];
            float a3 = ap[8 * AS_STRIDE + 4];
            split_tf32(a0, Ah[mt][0], Al[mt][0]);
            split_tf32(a1, Ah[mt][1], Al[mt][1]);
            split_tf32(a2, Ah[mt][2], Al[mt][2]);
            split_tf32(a3, Ah[mt][3], Al[mt][3]);
        }

        uint32_t Bh[8][2], Bl[8][2];
#pragma unroll
        for (int nt = 0; nt < 8; nt++) {
            int nbase = warpN * 64 + nt * 8;
            const float* bp = Ws + (k0 + tig) * WS_STRIDE + nbase + grp;
            float b0 = bp[0];
            float b1 = bp[4 * WS_STRIDE];
            split_tf32(b0, Bh[nt][0], Bl[nt][0]);
            split_tf32(b1, Bh[nt][1], Bl[nt][1]);
        }

#pragma unroll
        for (int mt = 0; mt < 2; mt++)
#pragma unroll
            for (int nt = 0; nt < 8; nt++) {
                mma_tf32(C[mt][nt], Ah[mt][0], Ah[mt][1], Ah[mt][2], Ah[mt][3],
                         Bh[nt][0], Bh[nt][1]);
                mma_tf32(C[mt][nt], Al[mt][0], Al[mt][1], Al[mt][2], Al[mt][3],
                         Bh[nt][0], Bh[nt][1]);
                mma_tf32(C[mt][nt], Ah[mt][0], Ah[mt][1], Ah[mt][2], Ah[mt][3],
                         Bl[nt][0], Bl[nt][1]);
            }
    }

    // ---- store feat ----
#pragma unroll
    for (int mt = 0; mt < 2; mt++) {
        int row0 = rowBase + warpM * 32 + mt * 16 + grp;
#pragma unroll
        for (int nt = 0; nt < 8; nt++) {
            int col = warpN * 64 + nt * 8 + 2 * tig;
            if (row0 < N)
                *(float2*)&g_feat[(size_t)row0 * 128 + col] =
                    make_float2(C[mt][nt][0], C[mt][nt][1]);
            if (row0 + 8 < N)
                *(float2*)&g_feat[(size_t)(row0 + 8) * 128 + col] =
                    make_float2(C[mt][nt][2], C[mt][nt][3]);
        }
    }

    // ---- fused el/er epilogue ----
    float alv[8][2], arv[8][2];
#pragma unroll
    for (int nt = 0; nt < 8; nt++) {
        int col = warpN * 64 + nt * 8 + 2 * tig;
        alv[nt][0] = __ldg(&attn_l[col]);
        alv[nt][1] = __ldg(&attn_l[col + 1]);
        arv[nt][0] = __ldg(&attn_r[col]);
        arv[nt][1] = __ldg(&attn_r[col + 1]);
    }

#pragma unroll
    for (int mt = 0; mt < 2; mt++) {
        int row0 = rowBase + warpM * 32 + mt * 16 + grp;
#pragma unroll
        for (int half = 0; half < 2; half++) {
            float pl[2] = {0.f, 0.f}, pr[2] = {0.f, 0.f};
#pragma unroll
            for (int nt = 0; nt < 8; nt++) {
                int hl = nt >> 2;
                float c0 = C[mt][nt][half * 2 + 0];
                float c1 = C[mt][nt][half * 2 + 1];
                pl[hl] = fmaf(c0, alv[nt][0], fmaf(c1, alv[nt][1], pl[hl]));
                pr[hl] = fmaf(c0, arv[nt][0], fmaf(c1, arv[nt][1], pr[hl]));
            }
#pragma unroll
            for (int hl = 0; hl < 2; hl++) {
                pl[hl] += __shfl_xor_sync(0xFFFFFFFFu, pl[hl], 1);
                pl[hl] += __shfl_xor_sync(0xFFFFFFFFu, pl[hl], 2);
                pr[hl] += __shfl_xor_sync(0xFFFFFFFFu, pr[hl], 1);
                pr[hl] += __shfl_xor_sync(0xFFFFFFFFu, pr[hl], 2);
            }
            int row = row0 + half * 8;
            if (tig == 0 && row < N) {
                int h0 = warpN * 2;
                g_el[row * 4 + h0 + 0] = pl[0];
                g_el[row * 4 + h0 + 1] = pl[1];
                g_er[row * 4 + h0 + 0] = pr[0];
                g_er[row * 4 + h0 + 1] = pr[1];
            }
        }
    }
}

// ---------------------------------------------------------------------------
// Scan A: per-1024-block exclusive scan of g_cnt -> g_off, totals -> g_bsum
// ---------------------------------------------------------------------------
__global__ void scanA_kernel(int N) {
    __shared__ int wtot[8];
    __shared__ int wexcl[8];
    int tid = threadIdx.x;
    int lane = tid & 31;
    int base = blockIdx.x * 1024 + tid * 4;

    int4 c = make_int4(0, 0, 0, 0);
    if (base + 3 < N) {
        c = *(const int4*)(g_cnt + base);
    } else {
        if (base + 0 < N) c.x = g_cnt[base + 0];
        if (base + 1 < N) c.y = g_cnt[base + 1];
        if (base + 2 < N) c.z = g_cnt[base + 2];
        if (base + 3 < N) c.w = g_cnt[base + 3];
    }
    int tsum = c.x + c.y + c.z + c.w;
    int incl = tsum;
#pragma unroll
    for (int s = 1; s < 32; s <<= 1) {
        int v = __shfl_up_sync(0xFFFFFFFFu, incl, s);
        if (lane >= s) incl += v;
    }
    if (lane == 31) wtot[tid >> 5] = incl;
    __syncthreads();
    if (tid == 0) {
        int r = 0;
#pragma unroll
        for (int w = 0; w < 8; w++) { wexcl[w] = r; r += wtot[w]; }
        g_bsum[blockIdx.x] = r;
    }
    __syncthreads();
    int p = wexcl[tid >> 5] + incl - tsum;
    if (base + 0 < N) g_off[base + 0] = p;
    if (base + 1 < N) g_off[base + 1] = p + c.x;
    if (base + 2 < N) g_off[base + 2] = p + c.x + c.y;
    if (base + 3 < N) g_off[base + 3] = p + c.x + c.y + c.z;
}

// ---------------------------------------------------------------------------
// Scan B: exclusive scan of block totals (single block, 128 threads)
// ---------------------------------------------------------------------------
__global__ void scanB_kernel(int nb) {
    __shared__ int wtot[4];
    __shared__ int wexcl[4];
    int t = threadIdx.x;
    int lane = t & 31;
    int v = (t < nb) ? g_bsum[t] : 0;
    int incl = v;
#pragma unroll
    for (int s = 1; s < 32; s <<= 1) {
        int u = __shfl_up_sync(0xFFFFFFFFu, incl, s);
        if (lane >= s) incl += u;
    }
    if (lane == 31) wtot[t >> 5] = incl;
    __syncthreads();
    if (t == 0) {
        int r = 0;
#pragma unroll
        for (int w = 0; w < 4; w++) { wexcl[w] = r; r += wtot[w]; }
    }
    __syncthreads();
    if (t < nb) g_boff[t] = wexcl[t >> 5] + incl - v;
}

// ---------------------------------------------------------------------------
// Kernel: permute src ids into dst-sorted order.
// Cursor IS g_off (atomicAdd returns slot); 2 edges/thread via int2 loads.
// ---------------------------------------------------------------------------
__global__ void edge_scatter_kernel(const int* __restrict__ src,
                                    const int* __restrict__ dst,
                                    int E) {
    int e = (blockIdx.x * blockDim.x + threadIdx.x) * 2;
    if (e + 1 < E) {
        int2 s2 = *(const int2*)(src + e);
        int2 d2 = *(const int2*)(dst + e);
        int r0 = atomicAdd(&g_off[d2.x], 1);
        g_srcs[__ldg(&g_boff[d2.x >> 10]) + r0] = s2.x;
        int r1 = atomicAdd(&g_off[d2.y], 1);
        g_srcs[__ldg(&g_boff[d2.y >> 10]) + r1] = s2.y;
    } else if (e < E) {
        int s = src[e];
        int d = dst[e];
        int r = atomicAdd(&g_off[d], 1);
        g_srcs[__ldg(&g_boff[d >> 10]) + r] = s;
    }
}

// ---------------------------------------------------------------------------
// Kernel: gather aggregation. One warp per dst node, 8-wide pipelined.
// After scatter, g_off[node] = segment END (local); start = end - cnt.
// ---------------------------------------------------------------------------
__global__ void __launch_bounds__(256)
aggregate_kernel(const float* __restrict__ bias,
                 float* __restrict__ out,
                 int N) {
    int node = (blockIdx.x * blockDim.x + threadIdx.x) >> 5;
    int lane = threadIdx.x & 31;
    if (node >= N) return;

    int cnt = g_cnt[node];
    int off = g_boff[node >> 10] + g_off[node] - cnt;   // segment start (global)
    int h = lane >> 3;

    float er_h = g_er[node * 4 + h];

    float4 acc = make_float4(0.f, 0.f, 0.f, 0.f);
    float den = 0.f;

    const float4* feat4 = (const float4*)g_feat;

    int i = 0;
    for (; i + 8 <= cnt; i += 8) {
        int s[8];
#pragma unroll
        for (int j = 0; j < 8; j++) s[j] = g_srcs[off + i + j];
        float4 f[8];
#pragma unroll
        for (int j = 0; j < 8; j++) f[j] = feat4[(size_t)s[j] * 32 + lane];
        float w[8];
#pragma unroll
        for (int j = 0; j < 8; j++) {
            float e = __ldg(&g_el[s[j] * 4 + h]) + er_h;
            e = e > 0.f ? e : NEG_SLOPE * e;
            w[j] = __expf(e);
        }
#pragma unroll
        for (int j = 0; j < 8; j++) {
            den += w[j];
            acc.x = fmaf(w[j], f[j].x, acc.x);
            acc.y = fmaf(w[j], f[j].y, acc.y);
            acc.z = fmaf(w[j], f[j].z, acc.z);
            acc.w = fmaf(w[j], f[j].w, acc.w);
        }
    }
    for (; i + 4 <= cnt; i += 4) {
        int s[4];
#pragma unroll
        for (int j = 0; j < 4; j++) s[j] = g_srcs[off + i + j];
        float4 f[4];
#pragma unroll
        for (int j = 0; j < 4; j++) f[j] = feat4[(size_t)s[j] * 32 + lane];
#pragma unroll
        for (int j = 0; j < 4; j++) {
            float e = __ldg(&g_el[s[j] * 4 + h]) + er_h;
            e = e > 0.f ? e : NEG_SLOPE * e;
            float wj = __expf(e);
            den += wj;
            acc.x = fmaf(wj, f[j].x, acc.x);
            acc.y = fmaf(wj, f[j].y, acc.y);
            acc.z = fmaf(wj, f[j].z, acc.z);
            acc.w = fmaf(wj, f[j].w, acc.w);
        }
    }
    for (; i < cnt; i++) {
        int s0 = g_srcs[off + i];
        float e0 = __ldg(&g_el[s0 * 4 + h]) + er_h;
        e0 = e0 > 0.f ? e0 : NEG_SLOPE * e0;
        float w0 = __expf(e0);
        float4 f0 = feat4[(size_t)s0 * 32 + lane];
        den += w0;
        acc.x = fmaf(w0, f0.x, acc.x);
        acc.y = fmaf(w0, f0.y, acc.y);
        acc.z = fmaf(w0, f0.z, acc.z);
        acc.w = fmaf(w0, f0.w, acc.w);
    }

    float inv = __fdividef(1.0f, fmaxf(den, 1e-9f));
    float4 bvec = ((const float4*)bias)[lane];
    acc.x = acc.x * inv + bvec.x;
    acc.y = acc.y * inv + bvec.y;
    acc.z = acc.z * inv + bvec.z;
    acc.w = acc.w * inv + bvec.w;
    acc.x = acc.x > 0.f ? acc.x : expm1f(acc.x);
    acc.y = acc.y > 0.f ? acc.y : expm1f(acc.y);
    acc.z = acc.z > 0.f ? acc.z : expm1f(acc.z);
    acc.w = acc.w > 0.f ? acc.w : expm1f(acc.w);
    __stcs(&((float4*)out)[(size_t)node * 32 + lane], acc);
}

// ---------------------------------------------------------------------------
// Launcher — sort chain forked onto a side stream, overlapping the GEMM.
// ---------------------------------------------------------------------------
extern "C" void kernel_launch(void* const* d_in, const int* in_sizes, int n_in,
                              void* d_out, int out_size) {
    const float* features = (const float*)d_in[0];
    const int*   src      = (const int*)d_in[1];
    const int*   dst      = (const int*)d_in[2];
    const float* W        = (const float*)d_in[3];
    const float* attn_l   = (const float*)d_in[4];
    const float* attn_r   = (const float*)d_in[5];
    const float* bias     = (const float*)d_in[6];
    float*       out      = (float*)d_out;

    int N = in_sizes[0] / 128;   // 100000
    int E = in_sizes[1];         // 1600000
    int nb = (N + 1023) / 1024;  // scan blocks

    static cudaStream_t s2 = nullptr;
    static cudaEvent_t evFork = nullptr, evJoin = nullptr;
    if (!s2) {
        cudaStreamCreateWithFlags(&s2, cudaStreamNonBlocking);
        cudaEventCreateWithFlags(&evFork, cudaEventDisableTiming);
        cudaEventCreateWithFlags(&evJoin, cudaEventDisableTiming);
        int smem = (128 * AS_STRIDE + 128 * WS_STRIDE) * 4;
        cudaFuncSetAttribute(gemm_kernel, cudaFuncAttributeMaxDynamicSharedMemorySize, smem);
    }

    // fork side stream from the (capture) default stream
    cudaEventRecord(evFork, 0);
    cudaStreamWaitEvent(s2, evFork, 0);

    // side stream: counting-sort chain (independent of GEMM)
    zero_kernel<<<(N + 255) / 256, 256, 0, s2>>>(N);
    hist_kernel<<<(E / 4 + 255) / 256, 256, 0, s2>>>(dst, E);
    scanA_kernel<<<nb, 256, 0, s2>>>(N);
    scanB_kernel<<<1, 128, 0, s2>>>(nb);
    edge_scatter_kernel<<<(E / 2 + 255) / 256, 256, 0, s2>>>(src, dst, E);
    cudaEventRecord(evJoin, s2);

    // default stream: tensor-core GEMM with fused el/er epilogue
    int smem = (128 * AS_STRIDE + 128 * WS_STRIDE) * 4;
    gemm_kernel<<<(N + 127) / 128, 256, smem>>>(features, W, attn_l, attn_r, N);

    // join, then aggregate
    cudaStreamWaitEvent(0, evJoin, 0);
    aggregate_kernel<<<(N + 7) / 8, 256>>>(bias, out, N);
}

// round 10
// speedup vs baseline: 1.0620x; 1.0620x over previous
#include <cuda_runtime.h>
#include <math.h>
#include <stdint.h>

// Problem constants (fixed-shape problem)
#define NN 100000
#define EEDGES 1600000
#define NEG_SLOPE 0.2f
#define NBLK_SCAN ((NN + 1023) / 1024)   // 98

// Padded smem strides (floats) for conflict-free mma fragment loads
#define AS_STRIDE 132   // mod 32 = 4
#define WS_STRIDE 136   // mod 32 = 8

// ---------------------------------------------------------------------------
// Scratch (device globals — allocation-free rule)
// ---------------------------------------------------------------------------
__device__ __align__(16) float g_feat[(size_t)NN * 128];   // projected features [N,H,D]
__device__ __align__(16) float g_el[(size_t)NN * 4];       // [N,H]
__device__ __align__(16) float g_er[(size_t)NN * 4];       // [N,H]
__device__ __align__(16) int   g_srcs[EEDGES];             // src id, dst-sorted
__device__ __align__(16) int   g_cnt[NN];                  // per-dst degree
__device__ __align__(16) int   g_off[NN];                  // offsets (cursor after scatter)
__device__ __align__(16) int   g_bsum[NBLK_SCAN + 32];     // per-scan-block totals
__device__ __align__(16) int   g_boff[NBLK_SCAN + 32];     // exclusive scan of block totals

// ---------------------------------------------------------------------------
// tf32 helpers
// ---------------------------------------------------------------------------
__device__ __forceinline__ uint32_t f2tf32(float x) {
    uint32_t r;
    asm("cvt.rna.tf32.f32 %0, %1;" : "=r"(r) : "f"(x));
    return r;
}
__device__ __forceinline__ void split_tf32(float x, uint32_t& hi, uint32_t& lo) {
    hi = f2tf32(x);
    lo = f2tf32(x - __uint_as_float(hi));
}
__device__ __forceinline__ void mma_tf32(float c[4],
                                         uint32_t a0, uint32_t a1, uint32_t a2, uint32_t a3,
                                         uint32_t b0, uint32_t b1) {
    asm("mma.sync.aligned.m16n8k8.row.col.f32.tf32.tf32.f32 "
        "{%0,%1,%2,%3},{%4,%5,%6,%7},{%8,%9},{%0,%1,%2,%3};"
        : "+f"(c[0]), "+f"(c[1]), "+f"(c[2]), "+f"(c[3])
        : "r"(a0), "r"(a1), "r"(a2), "r"(a3), "r"(b0), "r"(b1));
}

// ---------------------------------------------------------------------------
// Kernel: zero degree counters
// ---------------------------------------------------------------------------
__global__ void zero_kernel(int n) {
    int i = blockIdx.x * blockDim.x + threadIdx.x;
    if (i < n) g_cnt[i] = 0;
}

// ---------------------------------------------------------------------------
// Kernel: histogram of dst (4 edges per thread, int4 load)
// ---------------------------------------------------------------------------
__global__ void hist_kernel(const int* __restrict__ dst, int E) {
    int e = (blockIdx.x * blockDim.x + threadIdx.x) * 4;
    if (e + 3 < E) {
        int4 d4 = *(const int4*)(dst + e);
        atomicAdd(&g_cnt[d4.x], 1);
        atomicAdd(&g_cnt[d4.y], 1);
        atomicAdd(&g_cnt[d4.z], 1);
        atomicAdd(&g_cnt[d4.w], 1);
    } else {
        for (int k = e; k < E; k++) atomicAdd(&g_cnt[dst[k]], 1);
    }
}

// ---------------------------------------------------------------------------
// Scan A: per-1024-block exclusive scan of g_cnt -> g_off, totals -> g_bsum
// ---------------------------------------------------------------------------
__global__ void scanA_kernel(int N) {
    __shared__ int wtot[8];
    __shared__ int wexcl[8];
    int tid = threadIdx.x;
    int lane = tid & 31;
    int base = blockIdx.x * 1024 + tid * 4;

    int4 c = make_int4(0, 0, 0, 0);
    if (base + 3 < N) {
        c = *(const int4*)(g_cnt + base);
    } else {
        if (base + 0 < N) c.x = g_cnt[base + 0];
        if (base + 1 < N) c.y = g_cnt[base + 1];
        if (base + 2 < N) c.z = g_cnt[base + 2];
        if (base + 3 < N) c.w = g_cnt[base + 3];
    }
    int tsum = c.x + c.y + c.z + c.w;
    int incl = tsum;
#pragma unroll
    for (int s = 1; s < 32; s <<= 1) {
        int v = __shfl_up_sync(0xFFFFFFFFu, incl, s);
        if (lane >= s) incl += v;
    }
    if (lane == 31) wtot[tid >> 5] = incl;
    __syncthreads();
    if (tid == 0) {
        int r = 0;
#pragma unroll
        for (int w = 0; w < 8; w++) { wexcl[w] = r; r += wtot[w]; }
        g_bsum[blockIdx.x] = r;
    }
    __syncthreads();
    int p = wexcl[tid >> 5] + incl - tsum;
    if (base + 0 < N) g_off[base + 0] = p;
    if (base + 1 < N) g_off[base + 1] = p + c.x;
    if (base + 2 < N) g_off[base + 2] = p + c.x + c.y;
    if (base + 3 < N) g_off[base + 3] = p + c.x + c.y + c.z;
}

// ---------------------------------------------------------------------------
// Scan B: exclusive scan of block totals (single block, 128 threads)
// ---------------------------------------------------------------------------
__global__ void scanB_kernel(int nb) {
    __shared__ int wtot[4];
    __shared__ int wexcl[4];
    int t = threadIdx.x;
    int lane = t & 31;
    int v = (t < nb) ? g_bsum[t] : 0;
    int incl = v;
#pragma unroll
    for (int s = 1; s < 32; s <<= 1) {
        int u = __shfl_up_sync(0xFFFFFFFFu, incl, s);
        if (lane >= s) incl += u;
    }
    if (lane == 31) wtot[t >> 5] = incl;
    __syncthreads();
    if (t == 0) {
        int r = 0;
#pragma unroll
        for (int w = 0; w < 4; w++) { wexcl[w] = r; r += wtot[w]; }
    }
    __syncthreads();
    if (t < nb) g_boff[t] = wexcl[t >> 5] + incl - v;
}

// ---------------------------------------------------------------------------
// Kernel: GEMM via tensor cores (3xTF32), fused el/er epilogue.
// ---------------------------------------------------------------------------
__global__ void __launch_bounds__(256, 1)
gemm_kernel(const float* __restrict__ A,
            const float* __restrict__ W,
            const float* __restrict__ attn_l,
            const float* __restrict__ attn_r,
            int N) {
    extern __shared__ float sm[];
    float* As = sm;                       // [128][AS_STRIDE]
    float* Ws = sm + 128 * AS_STRIDE;     // [128][WS_STRIDE]  (Ws[k][n])

    int tid = threadIdx.x;
    int rowBase = blockIdx.x * 128;

    for (int i = tid; i < 128 * 32; i += 256) {
        int k = i >> 5, c4 = i & 31;
        float4 v = ((const float4*)W)[(size_t)k * 32 + c4];
        *(float4*)(Ws + k * WS_STRIDE + c4 * 4) = v;
    }
    for (int i = tid; i < 128 * 32; i += 256) {
        int r = i >> 5, c4 = i & 31;
        int gr = rowBase + r;
        float4 v = make_float4(0.f, 0.f, 0.f, 0.f);
        if (gr < N) v = ((const float4*)A)[(size_t)gr * 32 + c4];
        *(float4*)(As + r * AS_STRIDE + c4 * 4) = v;
    }
    __syncthreads();

    int wid  = tid >> 5;
    int lane = tid & 31;
    int grp  = lane >> 2;
    int tig  = lane & 3;
    int warpM = wid >> 1;
    int warpN = wid & 1;

    float C[2][8][4];
#pragma unroll
    for (int mt = 0; mt < 2; mt++)
#pragma unroll
        for (int nt = 0; nt < 8; nt++)
#pragma unroll
            for (int q = 0; q < 4; q++) C[mt][nt][q] = 0.f;

#pragma unroll 2
    for (int step = 0; step < 16; step++) {
        int k0 = step * 8;

        uint32_t Ah[2][4], Al[2][4];
#pragma unroll
        for (int mt = 0; mt < 2; mt++) {
            int mbase = warpM * 32 + mt * 16;
            const float* ap = As + (mbase + grp) * AS_STRIDE + k0 + tig;
            float a0 = ap[0];
            float a1 = ap[8 * AS_STRIDE];
            float a2 = ap[4];
            float a3 = ap[8 * AS_STRIDE + 4];
            split_tf32(a0, Ah[mt][0], Al[mt][0]);
            split_tf32(a1, Ah[mt][1], Al[mt][1]);
            split_tf32(a2, Ah[mt][2], Al[mt][2]);
            split_tf32(a3, Ah[mt][3], Al[mt][3]);
        }

        uint32_t Bh[8][2], Bl[8][2];
#pragma unroll
        for (int nt = 0; nt < 8; nt++) {
            int nbase = warpN * 64 + nt * 8;
            const float* bp = Ws + (k0 + tig) * WS_STRIDE + nbase + grp;
            float b0 = bp[0];
            float b1 = bp[4 * WS_STRIDE];
            split_tf32(b0, Bh[nt][0], Bl[nt][0]);
            split_tf32(b1, Bh[nt][1], Bl[nt][1]);
        }

#pragma unroll
        for (int mt = 0; mt < 2; mt++)
#pragma unroll
            for (int nt = 0; nt < 8; nt++) {
                mma_tf32(C[mt][nt], Ah[mt][0], Ah[mt][1], Ah[mt][2], Ah[mt][3],
                         Bh[nt][0], Bh[nt][1]);
                mma_tf32(C[mt][nt], Al[mt][0], Al[mt][1], Al[mt][2], Al[mt][3],
                         Bh[nt][0], Bh[nt][1]);
                mma_tf32(C[mt][nt], Ah[mt][0], Ah[mt][1], Ah[mt][2], Ah[mt][3],
                         Bl[nt][0], Bl[nt][1]);
            }
    }

    // ---- store feat ----
#pragma unroll
    for (int mt = 0; mt < 2; mt++) {
        int row0 = rowBase + warpM * 32 + mt * 16 + grp;
#pragma unroll
        for (int nt = 0; nt < 8; nt++) {
            int col = warpN * 64 + nt * 8 + 2 * tig;
            if (row0 < N)
                *(float2*)&g_feat[(size_t)row0 * 128 + col] =
                    make_float2(C[mt][nt][0], C[mt][nt][1]);
            if (row0 + 8 < N)
                *(float2*)&g_feat[(size_t)(row0 + 8) * 128 + col] =
                    make_float2(C[mt][nt][2], C[mt][nt][3]);
        }
    }

    // ---- fused el/er epilogue ----
    float alv[8][2], arv[8][2];
#pragma unroll
    for (int nt = 0; nt < 8; nt++) {
        int col = warpN * 64 + nt * 8 + 2 * tig;
        alv[nt][0] = __ldg(&attn_l[col]);
        alv[nt][1] = __ldg(&attn_l[col + 1]);
        arv[nt][0] = __ldg(&attn_r[col]);
        arv[nt][1] = __ldg(&attn_r[col + 1]);
    }

#pragma unroll
    for (int mt = 0; mt < 2; mt++) {
        int row0 = rowBase + warpM * 32 + mt * 16 + grp;
#pragma unroll
        for (int half = 0; half < 2; half++) {
            float pl[2] = {0.f, 0.f}, pr[2] = {0.f, 0.f};
#pragma unroll
            for (int nt = 0; nt < 8; nt++) {
                int hl = nt >> 2;
                float c0 = C[mt][nt][half * 2 + 0];
                float c1 = C[mt][nt][half * 2 + 1];
                pl[hl] = fmaf(c0, alv[nt][0], fmaf(c1, alv[nt][1], pl[hl]));
                pr[hl] = fmaf(c0, arv[nt][0], fmaf(c1, arv[nt][1], pr[hl]));
            }
#pragma unroll
            for (int hl = 0; hl < 2; hl++) {
                pl[hl] += __shfl_xor_sync(0xFFFFFFFFu, pl[hl], 1);
                pl[hl] += __shfl_xor_sync(0xFFFFFFFFu, pl[hl], 2);
                pr[hl] += __shfl_xor_sync(0xFFFFFFFFu, pr[hl], 1);
                pr[hl] += __shfl_xor_sync(0xFFFFFFFFu, pr[hl], 2);
            }
            int row = row0 + half * 8;
            if (tig == 0 && row < N) {
                int h0 = warpN * 2;
                g_el[row * 4 + h0 + 0] = pl[0];
                g_el[row * 4 + h0 + 1] = pl[1];
                g_er[row * 4 + h0 + 0] = pr[0];
                g_er[row * 4 + h0 + 1] = pr[1];
            }
        }
    }
}

// ---------------------------------------------------------------------------
// Kernel: permute src ids into dst-sorted order.
// Cursor IS g_off (atomicAdd returns slot); 2 edges/thread via int2 loads.
// ---------------------------------------------------------------------------
__global__ void edge_scatter_kernel(const int* __restrict__ src,
                                    const int* __restrict__ dst,
                                    int E) {
    int e = (blockIdx.x * blockDim.x + threadIdx.x) * 2;
    if (e + 1 < E) {
        int2 s2 = *(const int2*)(src + e);
        int2 d2 = *(const int2*)(dst + e);
        int r0 = atomicAdd(&g_off[d2.x], 1);
        g_srcs[__ldg(&g_boff[d2.x >> 10]) + r0] = s2.x;
        int r1 = atomicAdd(&g_off[d2.y], 1);
        g_srcs[__ldg(&g_boff[d2.y >> 10]) + r1] = s2.y;
    } else if (e < E) {
        int s = src[e];
        int d = dst[e];
        int r = atomicAdd(&g_off[d], 1);
        g_srcs[__ldg(&g_boff[d >> 10]) + r] = s;
    }
}

// ---------------------------------------------------------------------------
// Kernel: gather aggregation. One warp per dst node (4-wide pipelined).
// After scatter, g_off[node] = segment END (local); start = end - cnt.
// ---------------------------------------------------------------------------
__global__ void __launch_bounds__(256)
aggregate_kernel(const float* __restrict__ bias,
                 float* __restrict__ out,
                 int N) {
    int node = (blockIdx.x * blockDim.x + threadIdx.x) >> 5;
    int lane = threadIdx.x & 31;
    if (node >= N) return;

    int cnt = g_cnt[node];
    int off = g_boff[node >> 10] + g_off[node] - cnt;   // segment start (global)
    int h = lane >> 3;

    float er_h = g_er[node * 4 + h];

    float4 acc = make_float4(0.f, 0.f, 0.f, 0.f);
    float den = 0.f;

    const float4* feat4 = (const float4*)g_feat;

    int i = 0;
    for (; i + 4 <= cnt; i += 4) {
        int s0 = g_srcs[off + i + 0];
        int s1 = g_srcs[off + i + 1];
        int s2 = g_srcs[off + i + 2];
        int s3 = g_srcs[off + i + 3];
        float e0 = __ldg(&g_el[s0 * 4 + h]) + er_h;
        float e1 = __ldg(&g_el[s1 * 4 + h]) + er_h;
        float e2 = __ldg(&g_el[s2 * 4 + h]) + er_h;
        float e3 = __ldg(&g_el[s3 * 4 + h]) + er_h;
        float4 f0 = feat4[(size_t)s0 * 32 + lane];
        float4 f1 = feat4[(size_t)s1 * 32 + lane];
        float4 f2 = feat4[(size_t)s2 * 32 + lane];
        float4 f3 = feat4[(size_t)s3 * 32 + lane];
        e0 = e0 > 0.f ? e0 : NEG_SLOPE * e0;
        e1 = e1 > 0.f ? e1 : NEG_SLOPE * e1;
        e2 = e2 > 0.f ? e2 : NEG_SLOPE * e2;
        e3 = e3 > 0.f ? e3 : NEG_SLOPE * e3;
        float w0 = __expf(e0), w1 = __expf(e1), w2 = __expf(e2), w3 = __expf(e3);
        den += (w0 + w1) + (w2 + w3);
        acc.x = fmaf(w0, f0.x, acc.x); acc.y = fmaf(w0, f0.y, acc.y);
        acc.z = fmaf(w0, f0.z, acc.z); acc.w = fmaf(w0, f0.w, acc.w);
        acc.x = fmaf(w1, f1.x, acc.x); acc.y = fmaf(w1, f1.y, acc.y);
        acc.z = fmaf(w1, f1.z, acc.z); acc.w = fmaf(w1, f1.w, acc.w);
        acc.x = fmaf(w2, f2.x, acc.x); acc.y = fmaf(w2, f2.y, acc.y);
        acc.z = fmaf(w2, f2.z, acc.z); acc.w = fmaf(w2, f2.w, acc.w);
        acc.x = fmaf(w3, f3.x, acc.x); acc.y = fmaf(w3, f3.y, acc.y);
        acc.z = fmaf(w3, f3.z, acc.z); acc.w = fmaf(w3, f3.w, acc.w);
    }
    for (; i < cnt; i++) {
        int s0 = g_srcs[off + i];
        float e0 = __ldg(&g_el[s0 * 4 + h]) + er_h;
        e0 = e0 > 0.f ? e0 : NEG_SLOPE * e0;
        float w0 = __expf(e0);
        float4 f0 = feat4[(size_t)s0 * 32 + lane];
        den += w0;
        acc.x = fmaf(w0, f0.x, acc.x); acc.y = fmaf(w0, f0.y, acc.y);
        acc.z = fmaf(w0, f0.z, acc.z); acc.w = fmaf(w0, f0.w, acc.w);
    }

    float inv = __fdividef(1.0f, fmaxf(den, 1e-9f));
    float4 bvec = ((const float4*)bias)[lane];
    acc.x = acc.x * inv + bvec.x;
    acc.y = acc.y * inv + bvec.y;
    acc.z = acc.z * inv + bvec.z;
    acc.w = acc.w * inv + bvec.w;
    acc.x = acc.x > 0.f ? acc.x : expm1f(acc.x);
    acc.y = acc.y > 0.f ? acc.y : expm1f(acc.y);
    acc.z = acc.z > 0.f ? acc.z : expm1f(acc.z);
    acc.w = acc.w > 0.f ? acc.w : expm1f(acc.w);
    __stcs(&((float4*)out)[(size_t)node * 32 + lane], acc);
}

// ---------------------------------------------------------------------------
// Launcher.  Submission order makes gemm the 4th kernel (ncu profiles #4).
// ---------------------------------------------------------------------------
extern "C" void kernel_launch(void* const* d_in, const int* in_sizes, int n_in,
                              void* d_out, int out_size) {
    const float* features = (const float*)d_in[0];
    const int*   src      = (const int*)d_in[1];
    const int*   dst      = (const int*)d_in[2];
    const float* W        = (const float*)d_in[3];
    const float* attn_l   = (const float*)d_in[4];
    const float* attn_r   = (const float*)d_in[5];
    const float* bias     = (const float*)d_in[6];
    float*       out      = (float*)d_out;

    int N = in_sizes[0] / 128;   // 100000
    int E = in_sizes[1];         // 1600000
    int nb = (N + 1023) / 1024;  // scan blocks

    static cudaStream_t s2 = nullptr;
    static cudaEvent_t evFork = nullptr, evJoin = nullptr;
    if (!s2) {
        cudaStreamCreateWithFlags(&s2, cudaStreamNonBlocking);
        cudaEventCreateWithFlags(&evFork, cudaEventDisableTiming);
        cudaEventCreateWithFlags(&evJoin, cudaEventDisableTiming);
        int smem = (128 * AS_STRIDE + 128 * WS_STRIDE) * 4;
        cudaFuncSetAttribute(gemm_kernel, cudaFuncAttributeMaxDynamicSharedMemorySize, smem);
    }

    // fork side stream from the (capture) default stream
    cudaEventRecord(evFork, 0);
    cudaStreamWaitEvent(s2, evFork, 0);

    // side stream: zero + hist + scanA (kernels 1-3)
    zero_kernel<<<(N + 255) / 256, 256, 0, s2>>>(N);
    hist_kernel<<<(E / 4 + 255) / 256, 256, 0, s2>>>(dst, E);
    scanA_kernel<<<nb, 256, 0, s2>>>(N);

    // default stream: tensor-core GEMM (kernel 4 — profiled by ncu)
    int smem = (128 * AS_STRIDE + 128 * WS_STRIDE) * 4;
    gemm_kernel<<<(N + 127) / 128, 256, smem>>>(features, W, attn_l, attn_r, N);

    // side stream: scanB + scatter (kernels 5-6)
    scanB_kernel<<<1, 128, 0, s2>>>(nb);
    edge_scatter_kernel<<<(E / 2 + 255) / 256, 256, 0, s2>>>(src, dst, E);
    cudaEventRecord(evJoin, s2);

    // join, then aggregate (kernel 7)
    cudaStreamWaitEvent(0, evJoin, 0);
    aggregate_kernel<<<(N + 7) / 8, 256>>>(bias, out, N);
}

// round 11
// speedup vs baseline: 1.2585x; 1.1850x over previous
#include <cuda_runtime.h>
#include <math.h>
#include <stdint.h>

// Problem constants (fixed-shape problem)
#define NN 100000
#define EEDGES 1600000
#define NEG_SLOPE 0.2f
#define NBLK_SCAN ((NN + 1023) / 1024)   // 98

// Padded smem strides (floats) for conflict-free mma fragment loads
#define AS_STRIDE 132   // mod 32 = 4
#define WS_STRIDE 136   // mod 32 = 8
#define M_TILE 64

// ---------------------------------------------------------------------------
// Scratch (device globals — allocation-free rule)
// ---------------------------------------------------------------------------
__device__ __align__(16) float g_feat[(size_t)NN * 128];   // projected features [N,H,D]
__device__ __align__(16) float g_el[(size_t)NN * 4];       // [N,H]
__device__ __align__(16) float g_er[(size_t)NN * 4];       // [N,H]
__device__ __align__(16) int   g_srcs[EEDGES];             // src id, dst-sorted
__device__ __align__(16) int   g_cnt[NN];                  // per-dst degree
__device__ __align__(16) int   g_off[NN];                  // offsets (cursor after scatter)
__device__ __align__(16) int   g_bsum[NBLK_SCAN + 32];     // per-scan-block totals
__device__ __align__(16) int   g_boff[NBLK_SCAN + 32];     // exclusive scan of block totals

// ---------------------------------------------------------------------------
// tf32 helpers
// ---------------------------------------------------------------------------
__device__ __forceinline__ uint32_t f2tf32(float x) {
    uint32_t r;
    asm("cvt.rna.tf32.f32 %0, %1;" : "=r"(r) : "f"(x));
    return r;
}
__device__ __forceinline__ void split_tf32(float x, uint32_t& hi, uint32_t& lo) {
    hi = f2tf32(x);
    lo = f2tf32(x - __uint_as_float(hi));
}
__device__ __forceinline__ void mma_tf32(float c[4],
                                         uint32_t a0, uint32_t a1, uint32_t a2, uint32_t a3,
                                         uint32_t b0, uint32_t b1) {
    asm("mma.sync.aligned.m16n8k8.row.col.f32.tf32.tf32.f32 "
        "{%0,%1,%2,%3},{%4,%5,%6,%7},{%8,%9},{%0,%1,%2,%3};"
        : "+f"(c[0]), "+f"(c[1]), "+f"(c[2]), "+f"(c[3])
        : "r"(a0), "r"(a1), "r"(a2), "r"(a3), "r"(b0), "r"(b1));
}

// ---------------------------------------------------------------------------
// Kernel: zero degree counters
// ---------------------------------------------------------------------------
__global__ void zero_kernel(int n) {
    int i = blockIdx.x * blockDim.x + threadIdx.x;
    if (i < n) g_cnt[i] = 0;
}

// ---------------------------------------------------------------------------
// Kernel: histogram of dst (4 edges per thread, int4 load)
// ---------------------------------------------------------------------------
__global__ void hist_kernel(const int* __restrict__ dst, int E) {
    int e = (blockIdx.x * blockDim.x + threadIdx.x) * 4;
    if (e + 3 < E) {
        int4 d4 = *(const int4*)(dst + e);
        atomicAdd(&g_cnt[d4.x], 1);
        atomicAdd(&g_cnt[d4.y], 1);
        atomicAdd(&g_cnt[d4.z], 1);
        atomicAdd(&g_cnt[d4.w], 1);
    } else {
        for (int k = e; k < E; k++) atomicAdd(&g_cnt[dst[k]], 1);
    }
}

// ---------------------------------------------------------------------------
// Scan A: per-1024-block exclusive scan of g_cnt -> g_off, totals -> g_bsum
// ---------------------------------------------------------------------------
__global__ void scanA_kernel(int N) {
    __shared__ int wtot[8];
    __shared__ int wexcl[8];
    int tid = threadIdx.x;
    int lane = tid & 31;
    int base = blockIdx.x * 1024 + tid * 4;

    int4 c = make_int4(0, 0, 0, 0);
    if (base + 3 < N) {
        c = *(const int4*)(g_cnt + base);
    } else {
        if (base + 0 < N) c.x = g_cnt[base + 0];
        if (base + 1 < N) c.y = g_cnt[base + 1];
        if (base + 2 < N) c.z = g_cnt[base + 2];
        if (base + 3 < N) c.w = g_cnt[base + 3];
    }
    int tsum = c.x + c.y + c.z + c.w;
    int incl = tsum;
#pragma unroll
    for (int s = 1; s < 32; s <<= 1) {
        int v = __shfl_up_sync(0xFFFFFFFFu, incl, s);
        if (lane >= s) incl += v;
    }
    if (lane == 31) wtot[tid >> 5] = incl;
    __syncthreads();
    if (tid == 0) {
        int r = 0;
#pragma unroll
        for (int w = 0; w < 8; w++) { wexcl[w] = r; r += wtot[w]; }
        g_bsum[blockIdx.x] = r;
    }
    __syncthreads();
    int p = wexcl[tid >> 5] + incl - tsum;
    if (base + 0 < N) g_off[base + 0] = p;
    if (base + 1 < N) g_off[base + 1] = p + c.x;
    if (base + 2 < N) g_off[base + 2] = p + c.x + c.y;
    if (base + 3 < N) g_off[base + 3] = p + c.x + c.y + c.z;
}

// ---------------------------------------------------------------------------
// Scan B: exclusive scan of block totals (single block, 128 threads)
// ---------------------------------------------------------------------------
__global__ void scanB_kernel(int nb) {
    __shared__ int wtot[4];
    __shared__ int wexcl[4];
    int t = threadIdx.x;
    int lane = t & 31;
    int v = (t < nb) ? g_bsum[t] : 0;
    int incl = v;
#pragma unroll
    for (int s = 1; s < 32; s <<= 1) {
        int u = __shfl_up_sync(0xFFFFFFFFu, incl, s);
        if (lane >= s) incl += u;
    }
    if (lane == 31) wtot[t >> 5] = incl;
    __syncthreads();
    if (t == 0) {
        int r = 0;
#pragma unroll
        for (int w = 0; w < 4; w++) { wexcl[w] = r; r += wtot[w]; }
    }
    __syncthreads();
    if (t < nb) g_boff[t] = wexcl[t >> 5] + incl - v;
}

// ---------------------------------------------------------------------------
// Kernel: GEMM via tensor cores (3xTF32), fused el/er epilogue.
// Block: 256 threads (8 warps), tile 64(M) x 128(N), K=128.
// Warp tile: 32(M) x 32(N).  warpM = wid>>2 (0..1), warpN = wid&3 (0..3).
// smem 103.4 KB -> 2 blocks/SM (16 warps) vs previous 134 KB / 1 block.
// Each warp's 32 cols = exactly one head (h = warpN): el/er via 2 shfls.
// ---------------------------------------------------------------------------
__global__ void __launch_bounds__(256, 2)
gemm_kernel(const float* __restrict__ A,
            const float* __restrict__ W,
            const float* __restrict__ attn_l,
            const float* __restrict__ attn_r,
            int N) {
    extern __shared__ float sm[];
    float* As = sm;                          // [M_TILE][AS_STRIDE]
    float* Ws = sm + M_TILE * AS_STRIDE;     // [128][WS_STRIDE]  (Ws[k][n])

    int tid = threadIdx.x;
    int rowBase = blockIdx.x * M_TILE;

    // Load W (k-major 128x128) into padded smem
    for (int i = tid; i < 128 * 32; i += 256) {
        int k = i >> 5, c4 = i & 31;
        float4 v = ((const float4*)W)[(size_t)k * 32 + c4];
        *(float4*)(Ws + k * WS_STRIDE + c4 * 4) = v;
    }
    // Load A tile (64 rows) into padded smem (guarded)
    for (int i = tid; i < M_TILE * 32; i += 256) {
        int r = i >> 5, c4 = i & 31;
        int gr = rowBase + r;
        float4 v = make_float4(0.f, 0.f, 0.f, 0.f);
        if (gr < N) v = ((const float4*)A)[(size_t)gr * 32 + c4];
        *(float4*)(As + r * AS_STRIDE + c4 * 4) = v;
    }
    __syncthreads();

    int wid  = tid >> 5;
    int lane = tid & 31;
    int grp  = lane >> 2;    // 0..7
    int tig  = lane & 3;     // 0..3
    int warpM = wid >> 2;    // 0..1  (32 rows each)
    int warpN = wid & 3;     // 0..3  (32 cols each == head warpN)

    float C[2][4][4];
#pragma unroll
    for (int mt = 0; mt < 2; mt++)
#pragma unroll
        for (int nt = 0; nt < 4; nt++)
#pragma unroll
            for (int q = 0; q < 4; q++) C[mt][nt][q] = 0.f;

#pragma unroll 2
    for (int step = 0; step < 16; step++) {
        int k0 = step * 8;

        // A fragments: row = mbase+grp (and +8), col = k0 + tig (and +4)
        uint32_t Ah[2][4], Al[2][4];
#pragma unroll
        for (int mt = 0; mt < 2; mt++) {
            int mbase = warpM * 32 + mt * 16;
            const float* ap = As + (mbase + grp) * AS_STRIDE + k0 + tig;
            float a0 = ap[0];
            float a1 = ap[8 * AS_STRIDE];
            float a2 = ap[4];
            float a3 = ap[8 * AS_STRIDE + 4];
            split_tf32(a0, Ah[mt][0], Al[mt][0]);
            split_tf32(a1, Ah[mt][1], Al[mt][1]);
            split_tf32(a2, Ah[mt][2], Al[mt][2]);
            split_tf32(a3, Ah[mt][3], Al[mt][3]);
        }

        // B fragments: k = k0 + tig (and +4), n = nbase + grp
        uint32_t Bh[4][2], Bl[4][2];
#pragma unroll
        for (int nt = 0; nt < 4; nt++) {
            int nbase = warpN * 32 + nt * 8;
            const float* bp = Ws + (k0 + tig) * WS_STRIDE + nbase + grp;
            float b0 = bp[0];
            float b1 = bp[4 * WS_STRIDE];
            split_tf32(b0, Bh[nt][0], Bl[nt][0]);
            split_tf32(b1, Bh[nt][1], Bl[nt][1]);
        }

#pragma unroll
        for (int mt = 0; mt < 2; mt++)
#pragma unroll
            for (int nt = 0; nt < 4; nt++) {
                mma_tf32(C[mt][nt], Ah[mt][0], Ah[mt][1], Ah[mt][2], Ah[mt][3],
                         Bh[nt][0], Bh[nt][1]);
                mma_tf32(C[mt][nt], Al[mt][0], Al[mt][1], Al[mt][2], Al[mt][3],
                         Bh[nt][0], Bh[nt][1]);
                mma_tf32(C[mt][nt], Ah[mt][0], Ah[mt][1], Ah[mt][2], Ah[mt][3],
                         Bl[nt][0], Bl[nt][1]);
            }
    }

    // ---- store feat ----
#pragma unroll
    for (int mt = 0; mt < 2; mt++) {
        int row0 = rowBase + warpM * 32 + mt * 16 + grp;
#pragma unroll
        for (int nt = 0; nt < 4; nt++) {
            int col = warpN * 32 + nt * 8 + 2 * tig;
            if (row0 < N)
                *(float2*)&g_feat[(size_t)row0 * 128 + col] =
                    make_float2(C[mt][nt][0], C[mt][nt][1]);
            if (row0 + 8 < N)
                *(float2*)&g_feat[(size_t)(row0 + 8) * 128 + col] =
                    make_float2(C[mt][nt][2], C[mt][nt][3]);
        }
    }

    // ---- fused el/er epilogue (head h = warpN) ----
    float alv[4][2], arv[4][2];
#pragma unroll
    for (int nt = 0; nt < 4; nt++) {
        int col = warpN * 32 + nt * 8 + 2 * tig;
        alv[nt][0] = __ldg(&attn_l[col]);
        alv[nt][1] = __ldg(&attn_l[col + 1]);
        arv[nt][0] = __ldg(&attn_r[col]);
        arv[nt][1] = __ldg(&attn_r[col + 1]);
    }

#pragma unroll
    for (int mt = 0; mt < 2; mt++) {
        int row0 = rowBase + warpM * 32 + mt * 16 + grp;
#pragma unroll
        for (int half = 0; half < 2; half++) {   // row0 (c0,c1) / row0+8 (c2,c3)
            float pl = 0.f, pr = 0.f;
#pragma unroll
            for (int nt = 0; nt < 4; nt++) {
                float c0 = C[mt][nt][half * 2 + 0];
                float c1 = C[mt][nt][half * 2 + 1];
                pl = fmaf(c0, alv[nt][0], fmaf(c1, alv[nt][1], pl));
                pr = fmaf(c0, arv[nt][0], fmaf(c1, arv[nt][1], pr));
            }
            pl += __shfl_xor_sync(0xFFFFFFFFu, pl, 1);
            pl += __shfl_xor_sync(0xFFFFFFFFu, pl, 2);
            pr += __shfl_xor_sync(0xFFFFFFFFu, pr, 1);
            pr += __shfl_xor_sync(0xFFFFFFFFu, pr, 2);
            int row = row0 + half * 8;
            if (tig == 0 && row < N) {
                g_el[row * 4 + warpN] = pl;
                g_er[row * 4 + warpN] = pr;
            }
        }
    }
}

// ---------------------------------------------------------------------------
// Kernel: permute src ids into dst-sorted order.
// Cursor IS g_off (atomicAdd returns slot); 2 edges/thread via int2 loads.
// ---------------------------------------------------------------------------
__global__ void edge_scatter_kernel(const int* __restrict__ src,
                                    const int* __restrict__ dst,
                                    int E) {
    int e = (blockIdx.x * blockDim.x + threadIdx.x) * 2;
    if (e + 1 < E) {
        int2 s2 = *(const int2*)(src + e);
        int2 d2 = *(const int2*)(dst + e);
        int r0 = atomicAdd(&g_off[d2.x], 1);
        g_srcs[__ldg(&g_boff[d2.x >> 10]) + r0] = s2.x;
        int r1 = atomicAdd(&g_off[d2.y], 1);
        g_srcs[__ldg(&g_boff[d2.y >> 10]) + r1] = s2.y;
    } else if (e < E) {
        int s = src[e];
        int d = dst[e];
        int r = atomicAdd(&g_off[d], 1);
        g_srcs[__ldg(&g_boff[d >> 10]) + r] = s;
    }
}

// ---------------------------------------------------------------------------
// Kernel: gather aggregation. One warp per dst node (4-wide pipelined).
// After scatter, g_off[node] = segment END (local); start = end - cnt.
// ---------------------------------------------------------------------------
__global__ void __launch_bounds__(256)
aggregate_kernel(const float* __restrict__ bias,
                 float* __restrict__ out,
                 int N) {
    int node = (blockIdx.x * blockDim.x + threadIdx.x) >> 5;
    int lane = threadIdx.x & 31;
    if (node >= N) return;

    int cnt = g_cnt[node];
    int off = g_boff[node >> 10] + g_off[node] - cnt;   // segment start (global)
    int h = lane >> 3;

    float er_h = g_er[node * 4 + h];

    float4 acc = make_float4(0.f, 0.f, 0.f, 0.f);
    float den = 0.f;

    const float4* feat4 = (const float4*)g_feat;

    int i = 0;
    for (; i + 4 <= cnt; i += 4) {
        int s0 = g_srcs[off + i + 0];
        int s1 = g_srcs[off + i + 1];
        int s2 = g_srcs[off + i + 2];
        int s3 = g_srcs[off + i + 3];
        float e0 = __ldg(&g_el[s0 * 4 + h]) + er_h;
        float e1 = __ldg(&g_el[s1 * 4 + h]) + er_h;
        float e2 = __ldg(&g_el[s2 * 4 + h]) + er_h;
        float e3 = __ldg(&g_el[s3 * 4 + h]) + er_h;
        float4 f0 = feat4[(size_t)s0 * 32 + lane];
        float4 f1 = feat4[(size_t)s1 * 32 + lane];
        float4 f2 = feat4[(size_t)s2 * 32 + lane];
        float4 f3 = feat4[(size_t)s3 * 32 + lane];
        e0 = e0 > 0.f ? e0 : NEG_SLOPE * e0;
        e1 = e1 > 0.f ? e1 : NEG_SLOPE * e1;
        e2 = e2 > 0.f ? e2 : NEG_SLOPE * e2;
        e3 = e3 > 0.f ? e3 : NEG_SLOPE * e3;
        float w0 = __expf(e0), w1 = __expf(e1), w2 = __expf(e2), w3 = __expf(e3);
        den += (w0 + w1) + (w2 + w3);
        acc.x = fmaf(w0, f0.x, acc.x); acc.y = fmaf(w0, f0.y, acc.y);
        acc.z = fmaf(w0, f0.z, acc.z); acc.w = fmaf(w0, f0.w, acc.w);
        acc.x = fmaf(w1, f1.x, acc.x); acc.y = fmaf(w1, f1.y, acc.y);
        acc.z = fmaf(w1, f1.z, acc.z); acc.w = fmaf(w1, f1.w, acc.w);
        acc.x = fmaf(w2, f2.x, acc.x); acc.y = fmaf(w2, f2.y, acc.y);
        acc.z = fmaf(w2, f2.z, acc.z); acc.w = fmaf(w2, f2.w, acc.w);
        acc.x = fmaf(w3, f3.x, acc.x); acc.y = fmaf(w3, f3.y, acc.y);
        acc.z = fmaf(w3, f3.z, acc.z); acc.w = fmaf(w3, f3.w, acc.w);
    }
    for (; i < cnt; i++) {
        int s0 = g_srcs[off + i];
        float e0 = __ldg(&g_el[s0 * 4 + h]) + er_h;
        e0 = e0 > 0.f ? e0 : NEG_SLOPE * e0;
        float w0 = __expf(e0);
        float4 f0 = feat4[(size_t)s0 * 32 + lane];
        den += w0;
        acc.x = fmaf(w0, f0.x, acc.x); acc.y = fmaf(w0, f0.y, acc.y);
        acc.z = fmaf(w0, f0.z, acc.z); acc.w = fmaf(w0, f0.w, acc.w);
    }

    float inv = __fdividef(1.0f, fmaxf(den, 1e-9f));
    float4 bvec = ((const float4*)bias)[lane];
    acc.x = acc.x * inv + bvec.x;
    acc.y = acc.y * inv + bvec.y;
    acc.z = acc.z * inv + bvec.z;
    acc.w = acc.w * inv + bvec.w;
    acc.x = acc.x > 0.f ? acc.x : expm1f(acc.x);
    acc.y = acc.y > 0.f ? acc.y : expm1f(acc.y);
    acc.z = acc.z > 0.f ? acc.z : expm1f(acc.z);
    acc.w = acc.w > 0.f ? acc.w : expm1f(acc.w);
    __stcs(&((float4*)out)[(size_t)node * 32 + lane], acc);
}

// ---------------------------------------------------------------------------
// Launcher.  Submission order makes gemm the 4th kernel (ncu profiles #4).
// ---------------------------------------------------------------------------
extern "C" void kernel_launch(void* const* d_in, const int* in_sizes, int n_in,
                              void* d_out, int out_size) {
    const float* features = (const float*)d_in[0];
    const int*   src      = (const int*)d_in[1];
    const int*   dst      = (const int*)d_in[2];
    const float* W        = (const float*)d_in[3];
    const float* attn_l   = (const float*)d_in[4];
    const float* attn_r   = (const float*)d_in[5];
    const float* bias     = (const float*)d_in[6];
    float*       out      = (float*)d_out;

    int N = in_sizes[0] / 128;   // 100000
    int E = in_sizes[1];         // 1600000
    int nb = (N + 1023) / 1024;  // scan blocks

    static cudaStream_t s2 = nullptr;
    static cudaEvent_t evFork = nullptr, evJoin = nullptr;
    if (!s2) {
        cudaStreamCreateWithFlags(&s2, cudaStreamNonBlocking);
        cudaEventCreateWithFlags(&evFork, cudaEventDisableTiming);
        cudaEventCreateWithFlags(&evJoin, cudaEventDisableTiming);
        int smem = (M_TILE * AS_STRIDE + 128 * WS_STRIDE) * 4;
        cudaFuncSetAttribute(gemm_kernel, cudaFuncAttributeMaxDynamicSharedMemorySize, smem);
    }

    // fork side stream from the (capture) default stream
    cudaEventRecord(evFork, 0);
    cudaStreamWaitEvent(s2, evFork, 0);

    // side stream: zero + hist + scanA (kernels 1-3)
    zero_kernel<<<(N + 255) / 256, 256, 0, s2>>>(N);
    hist_kernel<<<(E / 4 + 255) / 256, 256, 0, s2>>>(dst, E);
    scanA_kernel<<<nb, 256, 0, s2>>>(N);

    // default stream: tensor-core GEMM (kernel 4 — profiled by ncu)
    int smem = (M_TILE * AS_STRIDE + 128 * WS_STRIDE) * 4;
    gemm_kernel<<<(N + M_TILE - 1) / M_TILE, 256, smem>>>(features, W, attn_l, attn_r, N);

    // side stream: scanB + scatter (kernels 5-6)
    scanB_kernel<<<1, 128, 0, s2>>>(nb);
    edge_scatter_kernel<<<(E / 2 + 255) / 256, 256, 0, s2>>>(src, dst, E);
    cudaEventRecord(evJoin, s2);

    // join, then aggregate (kernel 7)
    cudaStreamWaitEvent(0, evJoin, 0);
    aggregate_kernel<<<(N + 7) / 8, 256>>>(bias, out, N);
}